// round 8
// baseline (speedup 1.0000x reference)
#include <cuda_runtime.h>
#include <cstdint>

#define DINLINE __device__ __forceinline__

namespace {
constexpr int CIN = 512, PIX = 3136, NWIN = 8, WSTRIDE = 32;
constexpr int TM = 64;            // pixels per tile; 3136 = 49*64 exactly (no tail)
constexpr int TPC = 7, NBLK = 7;  // 49 tiles = 7 blocks x 7 tiles
constexpr int ROWF = 72;          // padded row stride in floats (bank-conflict-free)
constexpr int ROWB = ROWF * 4;    // 288 B
constexpr int BUFB = 64 * ROWB;   // 18432 B per x buffer
constexpr int SM_B = 0;           // B image: 16384 B
constexpr int SM_X = 16384;       // two x buffers
constexpr int SMEM_TOTAL = SM_X + 2 * BUFB;  // 53248 B
}

// W fragments (tf32-rounded fp32 bits), fragment order:
// idx = ng*2048 + ks*256 + j*64 + r*32 + lane
// n = ng*32 + j*8 + (lane>>2), k = ks*8 + (lane&3) + r*4
__device__ __align__(16) uint32_t g_wB[4096];

DINLINE uint32_t f2tf32(float f) {
    uint32_t r;
    asm("cvt.rna.tf32.f32 %0, %1;" : "=r"(r) : "f"(f));
    return r;
}

__global__ void prep_w(const float* __restrict__ w) {
    int t = threadIdx.x;
#pragma unroll
    for (int i = 0; i < 16; i++) {
        int idx  = i * 256 + t;
        int lane = idx & 31;
        int r    = (idx >> 5) & 1;
        int j    = (idx >> 6) & 3;
        int ks   = (idx >> 8) & 7;
        int ng   = (idx >> 11) & 1;
        int n = ng * 32 + j * 8 + (lane >> 2);
        int k = ks * 8 + (lane & 3) + r * 4;
        g_wB[idx] = f2tf32(w[n * 64 + k]);
    }
}

// ---- PTX helpers ----
DINLINE uint32_t smem_u32(const void* p) {
    uint32_t a;
    asm("{ .reg .u64 t; cvta.to.shared.u64 t, %1; cvt.u32.u64 %0, t; }" : "=r"(a) : "l"(p));
    return a;
}
DINLINE void cp16(uint32_t dst, const void* src) {
    asm volatile("cp.async.cg.shared.global [%0], [%1], 16;" :: "r"(dst), "l"(src) : "memory");
}
DINLINE float lds32(uint32_t a) {
    float f;
    asm volatile("ld.shared.f32 %0, [%1];" : "=f"(f) : "r"(a));
    return f;
}
DINLINE uint32_t ldsu32(uint32_t a) {
    uint32_t v;
    asm volatile("ld.shared.b32 %0, [%1];" : "=r"(v) : "r"(a));
    return v;
}
DINLINE void mma_tf32(float* c, uint32_t a0, uint32_t a1, uint32_t a2, uint32_t a3,
                      uint32_t b0, uint32_t b1) {
    asm volatile(
        "mma.sync.aligned.m16n8k8.row.col.f32.tf32.tf32.f32 "
        "{%0,%1,%2,%3}, {%4,%5,%6,%7}, {%8,%9}, {%0,%1,%2,%3};"
        : "+f"(c[0]), "+f"(c[1]), "+f"(c[2]), "+f"(c[3])
        : "r"(a0), "r"(a1), "r"(a2), "r"(a3), "r"(b0), "r"(b1));
}

__global__ void __launch_bounds__(256, 4)
win_mma(const float* __restrict__ x, float* __restrict__ out) {
    extern __shared__ __align__(16) char smem[];
    const uint32_t sb = smem_u32(smem);
    const int t = threadIdx.x;
    const int lane = t & 31, w = t >> 5;
    const int mg = w & 3, ng = w >> 2;     // 4 M16-groups x 2 N32-groups
    const int nwin = blockIdx.y, b = blockIdx.z;
    const int tile0 = blockIdx.x * TPC;

    // ---- copy B image to smem once per CTA (16KB) ----
    {
        const uint4* src = (const uint4*)g_wB;
        uint4* dst = (uint4*)(smem + SM_B);
#pragma unroll
        for (int i = 0; i < 4; i++) dst[i * 256 + t] = src[i * 256 + t];
    }

    // staging: 1024 chunks of 16B per tile, 4 per thread
    const float* xb = x + ((size_t)(b * CIN + nwin * WSTRIDE)) * PIX;
    const int sk = t >> 4;          // base k-row; rows step 16 per i
    const int sc = t & 15;          // chunk col
    // A-fragment lane pieces
    const int pA = mg * 16 + (lane >> 2);
    const int kA = lane & 3;
    // B-fragment base (conflict-free: lane-consecutive)
    const uint32_t bB = sb + SM_B + (uint32_t)(ng * 2048 + lane) * 4;
    // epilogue pieces
    const int grp = lane >> 2, tid4 = lane & 3;
    float* ob = out + ((size_t)(b * CIN + nwin)) * PIX;

    // ---- prologue: stage tile0 into buffer 0 ----
    {
        const float* src = xb + (size_t)sk * PIX + tile0 * TM + sc * 4;
        uint32_t dst = sb + SM_X + sk * ROWB + sc * 16;
#pragma unroll
        for (int i = 0; i < 4; i++)
            cp16(dst + i * 16 * ROWB, src + (size_t)(i * 16) * PIX);
        asm volatile("cp.async.commit_group;" ::: "memory");
    }

    for (int it = 0; it < TPC; it++) {
        // stage next tile into the other buffer
        if (it + 1 < TPC) {
            const float* src = xb + (size_t)sk * PIX + (tile0 + it + 1) * TM + sc * 4;
            uint32_t dst = sb + SM_X + ((it + 1) & 1) * BUFB + sk * ROWB + sc * 16;
#pragma unroll
            for (int i = 0; i < 4; i++)
                cp16(dst + i * 16 * ROWB, src + (size_t)(i * 16) * PIX);
            asm volatile("cp.async.commit_group;" ::: "memory");
            asm volatile("cp.async.wait_group 1;" ::: "memory");
        } else {
            asm volatile("cp.async.wait_group 0;" ::: "memory");
        }
        __syncthreads();   // staged data (and B on it==0) visible to all warps

        // ---- MMA: warp tile M16 (rows mg*16..+15) x N32 (cols ng*32..+31) ----
        float acc[4][4];
#pragma unroll
        for (int j = 0; j < 4; j++)
#pragma unroll
            for (int i = 0; i < 4; i++) acc[j][i] = 0.0f;

        const uint32_t bufb = sb + SM_X + (it & 1) * BUFB;
#pragma unroll
        for (int ks = 0; ks < 8; ks++) {
            // A fragment from raw [k][px] fp32 buffer (conflict-free LDS.32)
            uint32_t a0a = bufb + (uint32_t)((ks * 8 + kA) * ROWB + pA * 4);
            uint32_t a0 = f2tf32(lds32(a0a));
            uint32_t a1 = f2tf32(lds32(a0a + 32));            // px +8
            uint32_t a2 = f2tf32(lds32(a0a + 4 * ROWB));      // k +4
            uint32_t a3 = f2tf32(lds32(a0a + 4 * ROWB + 32));
            // B fragments for this ks (8 conflict-free LDS.32)
            uint32_t bo = bB + (uint32_t)(ks * 256) * 4;
#pragma unroll
            for (int j = 0; j < 4; j++) {
                uint32_t b0 = ldsu32(bo + (uint32_t)(j * 64) * 4);
                uint32_t b1 = ldsu32(bo + (uint32_t)(j * 64 + 32) * 4);
                mma_tf32(acc[j], a0, a1, a2, a3, b0, b1);
            }
        }

        // ---- epilogue: direct STG (no guards — 49 exact tiles) ----
        {
            const int px0 = (tile0 + it) * TM + mg * 16 + grp;
#pragma unroll
            for (int j = 0; j < 4; j++) {
                int o = ng * 32 + j * 8 + tid4 * 2;
                size_t s0 = (size_t)(o * NWIN) * PIX;
                size_t s1 = s0 + (size_t)NWIN * PIX;
                ob[s0 + px0] = acc[j][0];
                ob[s1 + px0] = acc[j][1];
                ob[s0 + px0 + 8] = acc[j][2];
                ob[s1 + px0 + 8] = acc[j][3];
            }
        }
        __syncthreads();   // all reads of buf[it&1] done before restaging
    }
}

extern "C" void kernel_launch(void* const* d_in, const int* in_sizes, int n_in,
                              void* d_out, int out_size) {
    const float* x = (const float*)d_in[0];   // (32, 512, 56, 56) fp32
    const float* w = (const float*)d_in[1];   // (64, 64) fp32
    float* out = (float*)d_out;               // (32, 512, 56, 56) fp32

    cudaFuncSetAttribute(win_mma, cudaFuncAttributeMaxDynamicSharedMemorySize, SMEM_TOTAL);
    prep_w<<<1, 256>>>(w);
    dim3 grid(NBLK, NWIN, 32);
    win_mma<<<grid, 256, SMEM_TOTAL>>>(x, out);
}

// round 9
// speedup vs baseline: 1.2197x; 1.2197x over previous
#include <cuda_runtime.h>
#include <cstdint>

#define DINLINE __device__ __forceinline__

namespace {
constexpr int CIN = 512, PIX = 3136, NWIN = 8, WSTRIDE = 32;
constexpr int TM = 128;            // pixels per tile; 25 tiles, tile 24 half-valid
constexpr int NTILES = 25;
constexpr int NJOBS = 32 * NWIN * NTILES;  // 6400 jobs: (b, nwin, tile)
constexpr int NCTA = 296;          // 148 SMs x 2 CTAs (persistent)
constexpr int SPLIT = NJOBS - NCTA * (NJOBS / NCTA);  // 184 CTAs get +1 job
constexpr int JBASE = NJOBS / NCTA;                   // 21
constexpr int ROWF = 136;          // padded row stride (floats) — conflict-free
constexpr int ROWB = ROWF * 4;     // 544 B
constexpr int BUFB = 64 * ROWB;    // 34816 B per buffer
constexpr int SMEM_TOTAL = 3 * BUFB;  // 104448 B (3-stage)
}

// W fragments (tf32-rounded fp32 bits), register order:
// idx = ng*2048 + ((ks*4 + j)*2 + r)*32 + lane
// n = ng*32 + j*8 + (lane>>2), k = ks*8 + (lane&3) + r*4
__device__ __align__(16) uint32_t g_wB[4096];

DINLINE uint32_t f2tf32(float f) {
    uint32_t r;
    asm("cvt.rna.tf32.f32 %0, %1;" : "=r"(r) : "f"(f));
    return r;
}

__global__ void prep_w(const float* __restrict__ w) {
    int t = threadIdx.x;
#pragma unroll
    for (int i = 0; i < 16; i++) {
        int idx  = i * 256 + t;
        int lane = idx & 31;
        int r    = (idx >> 5) & 1;
        int j    = (idx >> 6) & 3;
        int ks   = (idx >> 8) & 7;
        int ng   = (idx >> 11) & 1;
        int n = ng * 32 + j * 8 + (lane >> 2);
        int k = ks * 8 + (lane & 3) + r * 4;
        g_wB[idx] = f2tf32(w[n * 64 + k]);
    }
}

// ---- PTX helpers ----
DINLINE uint32_t smem_u32(const void* p) {
    uint32_t a;
    asm("{ .reg .u64 t; cvta.to.shared.u64 t, %1; cvt.u32.u64 %0, t; }" : "=r"(a) : "l"(p));
    return a;
}
DINLINE void cp16(uint32_t dst, const void* src) {
    asm volatile("cp.async.cg.shared.global [%0], [%1], 16;" :: "r"(dst), "l"(src) : "memory");
}
DINLINE float lds32(uint32_t a) {
    float f;
    asm volatile("ld.shared.f32 %0, [%1];" : "=f"(f) : "r"(a));
    return f;
}
DINLINE void mma_tf32(float* c, uint32_t a0, uint32_t a1, uint32_t a2, uint32_t a3,
                      uint32_t b0, uint32_t b1) {
    asm volatile(
        "mma.sync.aligned.m16n8k8.row.col.f32.tf32.tf32.f32 "
        "{%0,%1,%2,%3}, {%4,%5,%6,%7}, {%8,%9}, {%0,%1,%2,%3};"
        : "+f"(c[0]), "+f"(c[1]), "+f"(c[2]), "+f"(c[3])
        : "r"(a0), "r"(a1), "r"(a2), "r"(a3), "r"(b0), "r"(b1));
}

__global__ void __launch_bounds__(256, 2)
win_mma(const float* __restrict__ x, float* __restrict__ out) {
    extern __shared__ __align__(16) char smem[];
    const uint32_t sb = smem_u32(smem);
    const int t = threadIdx.x;
    const int lane = t & 31, w = t >> 5;
    const int mg = w & 3, ng = w >> 2;     // 4 M32-groups x 2 N32-groups

    // ---- B fragments: K=64, N=32 per warp, loaded ONCE per kernel ----
    uint32_t bw[8][4][2];
    {
        const uint32_t* base = g_wB + ng * 2048 + lane;
#pragma unroll
        for (int ks = 0; ks < 8; ks++)
#pragma unroll
            for (int j = 0; j < 4; j++)
#pragma unroll
                for (int r = 0; r < 2; r++)
                    bw[ks][j][r] = base[((ks * 4 + j) * 2 + r) * 32];
    }

    // persistent job range (contiguous chunk)
    const int c = blockIdx.x;
    const int jbeg = (c < SPLIT) ? c * (JBASE + 1) : c * JBASE + SPLIT;
    const int jend = jbeg + JBASE + (c < SPLIT ? 1 : 0);

    // staging lane pieces: 2048 x 16B chunks per tile, 8 per thread
    const int sk = t >> 5, sc = t & 31;
    // A-fragment lane pieces
    const int pA = lane >> 2, kA = lane & 3;
    // epilogue pieces
    const int grp = lane >> 2, tid4 = lane & 3;

    // stage job j into buffer bi (no-op if j >= jend); always commit outside
    auto stage = [&](int j, int bi) {
        if (j < jend) {
            int tile = j % NTILES;
            int rr = j / NTILES;
            int nwin = rr & 7, b = rr >> 3;
            const float* src = x + ((size_t)(b * CIN + nwin * WSTRIDE + sk)) * PIX +
                               tile * TM + sc * 4;
            uint32_t dst = sb + bi * BUFB + sk * ROWB + sc * 16;
#pragma unroll
            for (int i = 0; i < 8; i++)
                cp16(dst + i * 8 * ROWB, src + (size_t)(i * 8) * PIX);
        }
        asm volatile("cp.async.commit_group;" ::: "memory");
    };

    // ---- prologue: depth-2 prefetch ----
    stage(jbeg, 0);
    stage(jbeg + 1, 1);

    for (int i = jbeg; i < jend; i++) {
        asm volatile("cp.async.wait_group 1;" ::: "memory");
        __syncthreads();   // job i's data visible; prior iter's reads done

        const int tile = i % NTILES;
        const int rr = i / NTILES;
        const int nwin = rr & 7, b = rr >> 3;

        // ---- MMA: warp tile M32 x N32 ----
        float acc[2][4][4];
#pragma unroll
        for (int mf = 0; mf < 2; mf++)
#pragma unroll
            for (int j = 0; j < 4; j++)
#pragma unroll
                for (int q = 0; q < 4; q++) acc[mf][j][q] = 0.0f;

        const uint32_t bufb = sb + ((i - jbeg) % 3) * BUFB;
#pragma unroll
        for (int ks = 0; ks < 8; ks++) {
#pragma unroll
            for (int mf = 0; mf < 2; mf++) {
                int px = mg * 32 + mf * 16 + pA;
                uint32_t a0a = bufb + (uint32_t)((ks * 8 + kA) * ROWB + px * 4);
                uint32_t a0 = f2tf32(lds32(a0a));
                uint32_t a1 = f2tf32(lds32(a0a + 32));            // px +8
                uint32_t a2 = f2tf32(lds32(a0a + 4 * ROWB));      // k +4
                uint32_t a3 = f2tf32(lds32(a0a + 4 * ROWB + 32));
#pragma unroll
                for (int j = 0; j < 4; j++)
                    mma_tf32(acc[mf][j], a0, a1, a2, a3, bw[ks][j][0], bw[ks][j][1]);
            }
        }

        // ---- epilogue: direct STG (guarded for the tail tile) ----
        float* ob = out + ((size_t)(b * CIN + nwin)) * PIX;
#pragma unroll
        for (int mf = 0; mf < 2; mf++) {
            const int px0 = tile * TM + mg * 32 + mf * 16 + grp;
            const bool v0 = px0 < PIX, v1 = (px0 + 8) < PIX;
#pragma unroll
            for (int j = 0; j < 4; j++) {
                int o = ng * 32 + j * 8 + tid4 * 2;
                size_t s0 = (size_t)(o * NWIN) * PIX;
                size_t s1 = s0 + (size_t)NWIN * PIX;
                if (v0) { ob[s0 + px0] = acc[mf][j][0]; ob[s1 + px0] = acc[mf][j][1]; }
                if (v1) { ob[s0 + px0 + 8] = acc[mf][j][2]; ob[s1 + px0 + 8] = acc[mf][j][3]; }
            }
        }

        // ---- stage job i+2 (buffer freed by sync at top of this iter) ----
        stage(i + 2, (i - jbeg + 2) % 3);
    }
}

extern "C" void kernel_launch(void* const* d_in, const int* in_sizes, int n_in,
                              void* d_out, int out_size) {
    const float* x = (const float*)d_in[0];   // (32, 512, 56, 56) fp32
    const float* w = (const float*)d_in[1];   // (64, 64) fp32
    float* out = (float*)d_out;               // (32, 512, 56, 56) fp32

    cudaFuncSetAttribute(win_mma, cudaFuncAttributeMaxDynamicSharedMemorySize, SMEM_TOTAL);
    prep_w<<<1, 256>>>(w);
    win_mma<<<NCTA, 256, SMEM_TOTAL>>>(x, out);
}

// round 12
// speedup vs baseline: 1.2661x; 1.0381x over previous
#include <cuda_runtime.h>
#include <cstdint>

#define DINLINE __device__ __forceinline__

namespace {
constexpr int CIN = 512, PIX = 3136, NWIN = 8, WSTRIDE = 32;
constexpr int TM = 128;            // pixels per tile; 25 tiles, tile 24 half-valid
constexpr int NTILES = 25;
constexpr int NJOBS = 32 * NWIN * NTILES;  // 6400 jobs: (b, nwin, tile)
constexpr int NCTA = 296;          // 148 SMs x 2 CTAs (persistent)
constexpr int SPLIT = NJOBS - NCTA * (NJOBS / NCTA);
constexpr int JBASE = NJOBS / NCTA;
constexpr int ROWF = 136;          // padded row stride (floats) — conflict-free
constexpr int ROWB = ROWF * 4;     // 544 B
constexpr int BUFB = 64 * ROWB;    // 34816 B per buffer
constexpr int SMEM_TOTAL = 3 * BUFB;  // 104448 B (3-stage)
}

// W fragments (tf32-rounded fp32 bits), register order:
// idx = ng*2048 + ((ks*4 + j)*2 + r)*32 + lane
// n = ng*32 + j*8 + (lane>>2), k = ks*8 + (lane&3) + r*4
__device__ __align__(16) uint32_t g_wB[4096];

DINLINE uint32_t f2tf32(float f) {
    uint32_t r;
    asm("cvt.rna.tf32.f32 %0, %1;" : "=r"(r) : "f"(f));
    return r;
}

__global__ void prep_w(const float* __restrict__ w) {
    int t = threadIdx.x;
#pragma unroll
    for (int i = 0; i < 16; i++) {
        int idx  = i * 256 + t;
        int lane = idx & 31;
        int r    = (idx >> 5) & 1;
        int j    = (idx >> 6) & 3;
        int ks   = (idx >> 8) & 7;
        int ng   = (idx >> 11) & 1;
        int n = ng * 32 + j * 8 + (lane >> 2);
        int k = ks * 8 + (lane & 3) + r * 4;
        g_wB[idx] = f2tf32(w[n * 64 + k]);
    }
}

// ---- PTX helpers ----
DINLINE uint32_t smem_u32(const void* p) {
    uint32_t a;
    asm("{ .reg .u64 t; cvta.to.shared.u64 t, %1; cvt.u32.u64 %0, t; }" : "=r"(a) : "l"(p));
    return a;
}
DINLINE void cp16(uint32_t dst, const void* src) {
    asm volatile("cp.async.cg.shared.global [%0], [%1], 16;" :: "r"(dst), "l"(src) : "memory");
}
// load fp32 bits and add half-ulp-of-tf32: MMA truncates low 13 bits -> RNA-equivalent
DINLINE uint32_t ldtf(uint32_t a) {
    uint32_t v;
    asm volatile("ld.shared.b32 %0, [%1];" : "=r"(v) : "r"(a));
    return v + 0x1000u;
}
DINLINE void mma_tf32(float* c, uint32_t a0, uint32_t a1, uint32_t a2, uint32_t a3,
                      uint32_t b0, uint32_t b1) {
    asm volatile(
        "mma.sync.aligned.m16n8k8.row.col.f32.tf32.tf32.f32 "
        "{%0,%1,%2,%3}, {%4,%5,%6,%7}, {%8,%9}, {%0,%1,%2,%3};"
        : "+f"(c[0]), "+f"(c[1]), "+f"(c[2]), "+f"(c[3])
        : "r"(a0), "r"(a1), "r"(a2), "r"(a3), "r"(b0), "r"(b1));
}

__global__ void __launch_bounds__(256, 2)
win_mma(const float* __restrict__ x, float* __restrict__ out) {
    extern __shared__ __align__(16) char smem[];
    const uint32_t sb = smem_u32(smem);
    const int t = threadIdx.x;
    const int lane = t & 31, w = t >> 5;
    const int mg = w & 3, ng = w >> 2;     // 4 M32-groups x 2 N32-groups

    // ---- B fragments: K=64, N=32 per warp, loaded ONCE per kernel ----
    uint32_t bw[8][4][2];
    {
        const uint32_t* base = g_wB + ng * 2048 + lane;
#pragma unroll
        for (int ks = 0; ks < 8; ks++)
#pragma unroll
            for (int j = 0; j < 4; j++)
#pragma unroll
                for (int r = 0; r < 2; r++)
                    bw[ks][j][r] = base[((ks * 4 + j) * 2 + r) * 32];
    }

    // persistent job range (contiguous chunk)
    const int c = blockIdx.x;
    const int jbeg = (c < SPLIT) ? c * (JBASE + 1) : c * JBASE + SPLIT;
    const int jend = jbeg + JBASE + (c < SPLIT ? 1 : 0);

    // staging lane pieces: 2048 x 16B chunks per tile, 8 per thread
    const int sk = t >> 5, sc = t & 31;
    // A-fragment lane pieces
    const int pA = lane >> 2, kA = lane & 3;
    // epilogue pieces
    const int grp = lane >> 2, tid4 = lane & 3;

    // stage job j into buffer bi (no-op if j >= jend); always commits a group
    auto stage = [&](int j, int bi) {
        if (j < jend) {
            int tile = j % NTILES;
            int rr = j / NTILES;
            int nwin = rr & 7, b = rr >> 3;
            const float* src = x + ((size_t)(b * CIN + nwin * WSTRIDE + sk)) * PIX +
                               tile * TM + sc * 4;
            uint32_t dst = sb + bi * BUFB + sk * ROWB + sc * 16;
#pragma unroll
            for (int i = 0; i < 8; i++)
                cp16(dst + i * 8 * ROWB, src + (size_t)(i * 8) * PIX);
        }
        asm volatile("cp.async.commit_group;" ::: "memory");
    };

    // ---- prologue: depth-2 prefetch ----
    stage(jbeg, 0);
    stage(jbeg + 1, 1);

    for (int i = jbeg; i < jend; i++) {
        asm volatile("cp.async.wait_group 1;" ::: "memory");
        __syncthreads();   // job i's data visible; prior iter's reads done

        const int tile = i % NTILES;
        const int rr = i / NTILES;
        const int nwin = rr & 7, b = rr >> 3;

        // ---- MMA: warp tile M32 x N32 ----
        float acc[2][4][4];
#pragma unroll
        for (int mf = 0; mf < 2; mf++)
#pragma unroll
            for (int j = 0; j < 4; j++)
#pragma unroll
                for (int q = 0; q < 4; q++) acc[mf][j][q] = 0.0f;

        const uint32_t bufb = sb + ((i - jbeg) % 3) * BUFB;
#pragma unroll
        for (int ks = 0; ks < 8; ks++) {
#pragma unroll
            for (int mf = 0; mf < 2; mf++) {
                int px = mg * 32 + mf * 16 + pA;
                uint32_t a0a = bufb + (uint32_t)((ks * 8 + kA) * ROWB + px * 4);
                uint32_t a0 = ldtf(a0a);
                uint32_t a1 = ldtf(a0a + 32);            // px +8
                uint32_t a2 = ldtf(a0a + 4 * ROWB);      // k +4
                uint32_t a3 = ldtf(a0a + 4 * ROWB + 32);
#pragma unroll
                for (int j = 0; j < 4; j++)
                    mma_tf32(acc[mf][j], a0, a1, a2, a3, bw[ks][j][0], bw[ks][j][1]);
            }
        }

        // ---- epilogue: direct STG (guarded for the tail tile) ----
        float* ob = out + ((size_t)(b * CIN + nwin)) * PIX;
#pragma unroll
        for (int mf = 0; mf < 2; mf++) {
            const int px0 = tile * TM + mg * 32 + mf * 16 + grp;
            const bool v0 = px0 < PIX, v1 = (px0 + 8) < PIX;
#pragma unroll
            for (int j = 0; j < 4; j++) {
                int o = ng * 32 + j * 8 + tid4 * 2;
                size_t s0 = (size_t)(o * NWIN) * PIX;
                size_t s1 = s0 + (size_t)NWIN * PIX;
                if (v0) { ob[s0 + px0] = acc[mf][j][0]; ob[s1 + px0] = acc[mf][j][1]; }
                if (v1) { ob[s0 + px0 + 8] = acc[mf][j][2]; ob[s1 + px0 + 8] = acc[mf][j][3]; }
            }
        }

        // ---- stage job i+2 (buffer freed by sync at top of this iter) ----
        stage(i + 2, (i - jbeg + 2) % 3);
    }
}

extern "C" void kernel_launch(void* const* d_in, const int* in_sizes, int n_in,
                              void* d_out, int out_size) {
    const float* x = (const float*)d_in[0];   // (32, 512, 56, 56) fp32
    const float* w = (const float*)d_in[1];   // (64, 64) fp32
    float* out = (float*)d_out;               // (32, 512, 56, 56) fp32

    cudaFuncSetAttribute(win_mma, cudaFuncAttributeMaxDynamicSharedMemorySize, SMEM_TOTAL);
    prep_w<<<1, 256>>>(w);
    win_mma<<<NCTA, 256, SMEM_TOTAL>>>(x, out);
}

// round 13
// speedup vs baseline: 1.3368x; 1.0558x over previous
#include <cuda_runtime.h>
#include <cstdint>

#define DINLINE __device__ __forceinline__

namespace {
constexpr int CIN = 512, PIX = 3136, NWIN = 8, WSTRIDE = 32;
constexpr int TM = 128;            // pixels per tile; 25 tiles, tile 24 half-valid
constexpr int NTILES = 25;
constexpr int NJOBS = 32 * NWIN * NTILES;  // 6400 jobs: (b, nwin, tile)
constexpr int NCTA = 296;          // 148 SMs x 2 CTAs (persistent)
constexpr int SPLIT = NJOBS - NCTA * (NJOBS / NCTA);
constexpr int JBASE = NJOBS / NCTA;
constexpr int ROWF = 136;          // padded row stride (floats) — conflict-free
constexpr int ROWB = ROWF * 4;     // 544 B
constexpr int BUFB = 64 * ROWB;    // 34816 B per buffer
constexpr int SMEM_TOTAL = 3 * BUFB;  // 104448 B (3-stage)
}

// W fragments (tf32-rounded fp32 bits), register order:
// idx = ng*2048 + ((ks*4 + j)*2 + r)*32 + lane
// n = ng*32 + j*8 + (lane>>2), k = ks*8 + (lane&3) + r*4
__device__ __align__(16) uint32_t g_wB[4096];

DINLINE uint32_t f2tf32(float f) {
    uint32_t r;
    asm("cvt.rna.tf32.f32 %0, %1;" : "=r"(r) : "f"(f));
    return r;
}

__global__ void prep_w(const float* __restrict__ w) {
    int t = threadIdx.x;
#pragma unroll
    for (int i = 0; i < 16; i++) {
        int idx  = i * 256 + t;
        int lane = idx & 31;
        int r    = (idx >> 5) & 1;
        int j    = (idx >> 6) & 3;
        int ks   = (idx >> 8) & 7;
        int ng   = (idx >> 11) & 1;
        int n = ng * 32 + j * 8 + (lane >> 2);
        int k = ks * 8 + (lane & 3) + r * 4;
        g_wB[idx] = f2tf32(w[n * 64 + k]);
    }
}

// ---- PTX helpers ----
DINLINE uint32_t smem_u32(const void* p) {
    uint32_t a;
    asm("{ .reg .u64 t; cvta.to.shared.u64 t, %1; cvt.u32.u64 %0, t; }" : "=r"(a) : "l"(p));
    return a;
}
DINLINE void cp16(uint32_t dst, const void* src) {
    asm volatile("cp.async.cg.shared.global [%0], [%1], 16;" :: "r"(dst), "l"(src) : "memory");
}
// load a pixel-pair (two fp32) and apply half-ulp-of-tf32 bias to both in one IADD64.
// Carry cannot cross the 32-bit boundary for any normal/subnormal float bits.
DINLINE void ldtf2(uint32_t& lo, uint32_t& hi, uint32_t a) {
    unsigned long long v;
    asm volatile("ld.shared.b64 %0, [%1];" : "=l"(v) : "r"(a));
    v += 0x0000100000001000ULL;
    lo = (uint32_t)v;
    hi = (uint32_t)(v >> 32);
}
DINLINE void mma_tf32(float* c, uint32_t a0, uint32_t a1, uint32_t a2, uint32_t a3,
                      uint32_t b0, uint32_t b1) {
    asm volatile(
        "mma.sync.aligned.m16n8k8.row.col.f32.tf32.tf32.f32 "
        "{%0,%1,%2,%3}, {%4,%5,%6,%7}, {%8,%9}, {%0,%1,%2,%3};"
        : "+f"(c[0]), "+f"(c[1]), "+f"(c[2]), "+f"(c[3])
        : "r"(a0), "r"(a1), "r"(a2), "r"(a3), "r"(b0), "r"(b1));
}

__global__ void __launch_bounds__(256, 2)
win_mma(const float* __restrict__ x, float* __restrict__ out) {
    extern __shared__ __align__(16) char smem[];
    const uint32_t sb = smem_u32(smem);
    const int t = threadIdx.x;
    const int lane = t & 31, w = t >> 5;
    const int mg = w & 3, ng = w >> 2;     // 4 M32-groups x 2 N32-groups

    // ---- B fragments: K=64, N=32 per warp, loaded ONCE per kernel ----
    uint32_t bw[8][4][2];
    {
        const uint32_t* base = g_wB + ng * 2048 + lane;
#pragma unroll
        for (int ks = 0; ks < 8; ks++)
#pragma unroll
            for (int j = 0; j < 4; j++)
#pragma unroll
                for (int r = 0; r < 2; r++)
                    bw[ks][j][r] = base[((ks * 4 + j) * 2 + r) * 32];
    }

    // persistent job range (contiguous chunk)
    const int c = blockIdx.x;
    const int jbeg = (c < SPLIT) ? c * (JBASE + 1) : c * JBASE + SPLIT;
    const int jend = jbeg + JBASE + (c < SPLIT ? 1 : 0);

    // staging lane pieces: 2048 x 16B chunks per tile, 8 per thread
    const int sk = t >> 5, sc = t & 31;
    // A-fragment lane pieces.
    // Row->pixel map: MMA row r -> local px 2*(r&7) + (r>>3), so rows grp and
    // grp+8 are the adjacent pixel pair (2*grp, 2*grp+1)  ->  LDS.64.
    const int grp = lane >> 2, tid4 = lane & 3;
    const int kA = tid4;
    const int pxpair = mg * 32 + 2 * grp;   // + mf*16
    float* const outb = out;

    // stage job j into buffer bi (no-op if j >= jend); always commits a group
    auto stage = [&](int j, int bi) {
        if (j < jend) {
            int tile = j % NTILES;
            int rr = j / NTILES;
            int nwin = rr & 7, b = rr >> 3;
            const float* src = x + ((size_t)(b * CIN + nwin * WSTRIDE + sk)) * PIX +
                               tile * TM + sc * 4;
            uint32_t dst = sb + bi * BUFB + sk * ROWB + sc * 16;
#pragma unroll
            for (int i = 0; i < 8; i++)
                cp16(dst + i * 8 * ROWB, src + (size_t)(i * 8) * PIX);
        }
        asm volatile("cp.async.commit_group;" ::: "memory");
    };

    // ---- prologue: depth-2 prefetch ----
    stage(jbeg, 0);
    stage(jbeg + 1, 1);

    for (int i = jbeg; i < jend; i++) {
        asm volatile("cp.async.wait_group 1;" ::: "memory");
        __syncthreads();   // job i's data visible; prior iter's reads done

        const int tile = i % NTILES;
        const int rr = i / NTILES;
        const int nwin = rr & 7, b = rr >> 3;

        // ---- MMA: warp tile M32 x N32 ----
        float acc[2][4][4];
#pragma unroll
        for (int mf = 0; mf < 2; mf++)
#pragma unroll
            for (int j = 0; j < 4; j++)
#pragma unroll
                for (int q = 0; q < 4; q++) acc[mf][j][q] = 0.0f;

        const uint32_t bufb = sb + ((i - jbeg) % 3) * BUFB;
#pragma unroll
        for (int ks = 0; ks < 8; ks++) {
#pragma unroll
            for (int mf = 0; mf < 2; mf++) {
                uint32_t a0a = bufb +
                    (uint32_t)((ks * 8 + kA) * ROWB + (pxpair + mf * 16) * 4);
                uint32_t a0, a1, a2, a3;
                ldtf2(a0, a1, a0a);              // rows grp, grp+8  (k)
                ldtf2(a2, a3, a0a + 4 * ROWB);   // rows grp, grp+8  (k+4)
#pragma unroll
                for (int j = 0; j < 4; j++)
                    mma_tf32(acc[mf][j], a0, a1, a2, a3, bw[ks][j][0], bw[ks][j][1]);
            }
        }

        // ---- epilogue: paired STG.64 per (o, pixel-pair); guarded for tail ----
        float* ob = outb + ((size_t)(b * CIN + nwin)) * PIX;
#pragma unroll
        for (int mf = 0; mf < 2; mf++) {
            const int px0 = tile * TM + pxpair + mf * 16;   // even; pair = px0, px0+1
            if (px0 + 1 < PIX) {
#pragma unroll
                for (int j = 0; j < 4; j++) {
                    int o = ng * 32 + j * 8 + tid4 * 2;
                    size_t s0 = (size_t)(o * NWIN) * PIX;
                    size_t s1 = s0 + (size_t)NWIN * PIX;
                    // c0 = (o, px0), c2 = (o, px0+1); c1/c3 at o+1
                    *(float2*)(ob + s0 + px0) = make_float2(acc[mf][j][0], acc[mf][j][2]);
                    *(float2*)(ob + s1 + px0) = make_float2(acc[mf][j][1], acc[mf][j][3]);
                }
            }
        }

        // ---- stage job i+2 (buffer freed by sync at top of this iter) ----
        stage(i + 2, (i - jbeg + 2) % 3);
    }
}

extern "C" void kernel_launch(void* const* d_in, const int* in_sizes, int n_in,
                              void* d_out, int out_size) {
    const float* x = (const float*)d_in[0];   // (32, 512, 56, 56) fp32
    const float* w = (const float*)d_in[1];   // (64, 64) fp32
    float* out = (float*)d_out;               // (32, 512, 56, 56) fp32

    cudaFuncSetAttribute(win_mma, cudaFuncAttributeMaxDynamicSharedMemorySize, SMEM_TOTAL);
    prep_w<<<1, 256>>>(w);
    win_mma<<<NCTA, 256, SMEM_TOTAL>>>(x, out);
}